// round 10
// baseline (speedup 1.0000x reference)
#include <cuda_runtime.h>
#include <math.h>

#define Bsz    2048
#define Hd     256
#define INd    64
#define KTERMS 8
#define ROWS   16
#define NCTAS  128
#define NTHR   128
#define PITCH  20          // floats per activation column slice (80B)

typedef unsigned long long ull;

// Pre-transposed weights (L2-resident)
__device__ float g_whT[Hd*Hd];     // whT[j*Hd+k]   = wh[k*Hd+j]
__device__ float g_woutT[Hd*Hd];   // woutT[j*Hd+k] = wout[k*Hd+j]
__device__ float g_wxT[INd*Hd];    // wxT[i*Hd+k]   = wx[k*INd+i]

// ---------------- packed f32x2 helpers ----------------
__device__ __forceinline__ ull pack2(float lo, float hi) {
    ull r; asm("mov.b64 %0, {%1,%2};" : "=l"(r) : "f"(lo), "f"(hi)); return r;
}
__device__ __forceinline__ void unpack2(ull v, float& lo, float& hi) {
    asm("mov.b64 {%0,%1}, %2;" : "=f"(lo), "=f"(hi) : "l"(v));
}
__device__ __forceinline__ ull fma2(ull a, ull b, ull c) {
    ull d; asm("fma.rn.f32x2 %0, %1, %2, %3;" : "=l"(d) : "l"(a), "l"(b), "l"(c)); return d;
}
__device__ __forceinline__ ull mul2(ull a, ull b) {
    ull d; asm("mul.rn.f32x2 %0, %1, %2;" : "=l"(d) : "l"(a), "l"(b)); return d;
}
__device__ __forceinline__ ull add2(ull a, ull b) {
    ull d; asm("add.rn.f32x2 %0, %1, %2;" : "=l"(d) : "l"(a), "l"(b)); return d;
}

struct Row4 { ull v[4]; };
__device__ __forceinline__ Row4 ldrow4(const float* p) {
    Row4 r;
    const ulonglong2* q = reinterpret_cast<const ulonglong2*>(p);
    ulonglong2 a = q[0], b = q[1];
    r.v[0]=a.x; r.v[1]=a.y; r.v[2]=b.x; r.v[3]=b.y;
    return r;
}

// Full-j gemm: j = 4*jhi + jlo, phys(j) = jhi + BLK*jlo.
// acc[ci*4+p] += Wt[j][col0+ci] * act[phys(j)][pair p of this sub]
template<int NJHI, int BLK>
__device__ __forceinline__ void gemmF(const float* __restrict__ Wt, int col0,
                                      const float* sIn, ull acc[16]) {
#pragma unroll
    for (int jlo = 0; jlo < 4; ++jlo) {
        const float* wp = Wt + jlo * Hd + col0;
        const float* sp = sIn + (jlo * BLK) * PITCH;
#pragma unroll 8
        for (int jhi = 0; jhi < NJHI; ++jhi) {
            float4 w4 = *reinterpret_cast<const float4*>(wp);
            Row4 v = ldrow4(sp);
            ull w0 = pack2(w4.x, w4.x), w1 = pack2(w4.y, w4.y);
            ull w2 = pack2(w4.z, w4.z), w3 = pack2(w4.w, w4.w);
#pragma unroll
            for (int p = 0; p < 4; ++p) {
                acc[p]    = fma2(w0, v.v[p], acc[p]);
                acc[4+p]  = fma2(w1, v.v[p], acc[4+p]);
                acc[8+p]  = fma2(w2, v.v[p], acc[8+p]);
                acc[12+p] = fma2(w3, v.v[p], acc[12+p]);
            }
            wp += 4 * Hd;
            sp += PITCH;
        }
    }
}

// Dual-activation gemm: shared weight stream, two accumulator sets.
template<int NJHI, int BLK>
__device__ __forceinline__ void gemmD(const float* __restrict__ Wt, int col0,
                                      const float* sIn1, const float* sIn2,
                                      ull acc1[16], ull acc2[16]) {
#pragma unroll
    for (int jlo = 0; jlo < 4; ++jlo) {
        const float* wp  = Wt + jlo * Hd + col0;
        const float* sp1 = sIn1 + (jlo * BLK) * PITCH;
        const float* sp2 = sIn2 + (jlo * BLK) * PITCH;
#pragma unroll 4
        for (int jhi = 0; jhi < NJHI; ++jhi) {
            float4 w4 = *reinterpret_cast<const float4*>(wp);
            Row4 v1 = ldrow4(sp1);
            Row4 v2 = ldrow4(sp2);
            ull w0 = pack2(w4.x, w4.x), w1 = pack2(w4.y, w4.y);
            ull w2 = pack2(w4.z, w4.z), w3 = pack2(w4.w, w4.w);
#pragma unroll
            for (int p = 0; p < 4; ++p) {
                acc1[p]    = fma2(w0, v1.v[p], acc1[p]);
                acc1[4+p]  = fma2(w1, v1.v[p], acc1[4+p]);
                acc1[8+p]  = fma2(w2, v1.v[p], acc1[8+p]);
                acc1[12+p] = fma2(w3, v1.v[p], acc1[12+p]);
                acc2[p]    = fma2(w0, v2.v[p], acc2[p]);
                acc2[4+p]  = fma2(w1, v2.v[p], acc2[4+p]);
                acc2[8+p]  = fma2(w2, v2.v[p], acc2[8+p]);
                acc2[12+p] = fma2(w3, v2.v[p], acc2[12+p]);
            }
            wp += 4 * Hd;
            sp1 += PITCH;
            sp2 += PITCH;
        }
    }
}

// store this thread's 4-u64 slice for column ci (2 STS.128)
__device__ __forceinline__ void stcol(float* base, int t64, int ci, int soff, const ull v[4]) {
    float* rowb = base + (t64 + (ci << 6)) * PITCH + soff;
    ulonglong2* p = reinterpret_cast<ulonglong2*>(rowb);
    p[0] = make_ulonglong2(v[0], v[1]);
    p[1] = make_ulonglong2(v[2], v[3]);
}

// ---------------- merged transpose ----------------
__global__ void transpose_all(const float* __restrict__ wh,
                              const float* __restrict__ wout,
                              const float* __restrict__ wx) {
    __shared__ float tile[32][33];
    int b = blockIdx.x;
    const float* in; float* out; int rows, cols, bx;
    if (b < 64)       { in = wh;   out = g_whT;   rows = Hd; cols = Hd;  bx = b; }
    else if (b < 128) { in = wout; out = g_woutT; rows = Hd; cols = Hd;  bx = b - 64; }
    else              { in = wx;   out = g_wxT;   rows = Hd; cols = INd; bx = b - 128; }
    int nbx = cols / 32;
    int c0 = (bx % nbx) * 32, r0 = (bx / nbx) * 32;
    for (int dy = threadIdx.y; dy < 32; dy += 8)
        tile[dy][threadIdx.x] = in[(r0 + dy) * cols + (c0 + threadIdx.x)];
    __syncthreads();
    for (int dy = threadIdx.y; dy < 32; dy += 8)
        out[(c0 + dy) * rows + (r0 + threadIdx.x)] = tile[threadIdx.x][dy];
}

// ---------------- fused vector-field kernel (full-dot threads, no merge) ----------------
__global__ void __launch_bounds__(NTHR)
fused_kernel(const float* __restrict__ hin, const float* __restrict__ xin,
             const float* __restrict__ xdin, const float* __restrict__ b0v,
             const float* __restrict__ b1v, float* __restrict__ out) {
    extern __shared__ __align__(16) float sm[];
    float* sA0 = sm;                    // [256][PITCH]
    float* sA1 = sA0 + Hd * PITCH;
    float* sB0 = sA1 + Hd * PITCH;
    float* sB1 = sB0 + Hd * PITCH;
    float* sXx = sB1 + Hd * PITCH;      // [64][PITCH]
    float* sXd = sXx + INd * PITCH;

    const int tid  = threadIdx.x;
    const int t64  = tid & 63;          // column-thread id
    const int sub  = tid >> 6;          // row sub-tile 0/1 (8 rows each)
    const int col0 = t64 << 2;
    const int soff = sub << 3;          // float offset of sub's slice within a column
    const int row0 = blockIdx.x * ROWS;

    // ---- stage inputs (transposed, phys-permuted: phys(j) = (j>>2) + (j&3)*BLK)
    for (int e = tid; e < ROWS * Hd; e += NTHR) {
        int r = e >> 8, j = e & 255;
        int pr = (j >> 2) + ((j & 3) << 6);
        sA0[pr * PITCH + r] = hin[(row0 + r) * Hd + j];
    }
    for (int e = tid; e < ROWS * INd; e += NTHR) {
        int r = e >> 6, i = e & 63;
        int pr = (i >> 2) + ((i & 3) << 4);
        sXx[pr * PITCH + r] = xin[(row0 + r) * INd + i];
        sXd[pr * PITCH + r] = xdin[(row0 + r) * INd + i];
    }
    __syncthreads();

    ull gate[16], dth[16], hd[16];

    // ---- P1: l1 = x@wxT + h@whT + b0 ; uu = xdot@wxT  (dual over wxT, single over whT)
    {
        ull l1[16], uu[16];
#pragma unroll
        for (int q = 0; q < 16; ++q) { l1[q] = 0ull; uu[q] = 0ull; }
        gemmD<16, 16>(g_wxT, col0, sXx + soff, sXd + soff, l1, uu);
        gemmF<64, 64>(g_whT, col0, sA0 + soff, l1);
        float4 bb = *reinterpret_cast<const float4*>(b0v + col0);
        float bks[4] = {bb.x, bb.y, bb.z, bb.w};
#pragma unroll
        for (int ci = 0; ci < 4; ++ci) {
            ull bp = pack2(bks[ci], bks[ci]);
            ull relu[4], gu[4];
#pragma unroll
            for (int p = 0; p < 4; ++p) {
                int q = ci * 4 + p;
                ull L = add2(l1[q], bp);
                float a, b; unpack2(L, a, b);
                float ga = (a > 0.f) ? 1.f : 0.f;
                float gb = (b > 0.f) ? 1.f : 0.f;
                gate[q] = pack2(ga, gb);
                relu[p] = pack2(ga * a, gb * b);
                gu[p]   = mul2(uu[q], gate[q]);
            }
            stcol(sB0, t64, ci, soff, relu);   // relu -> sB0
            stcol(sA1, t64, ci, soff, gu);     // gated-u -> sA1
        }
    }
    __syncthreads();

    // ---- P2: lout = relu@woutT + b1 -> dth ; jx = gated-u@woutT -> curr = dth*jx -> sA0
    {
        ull lo[16], jx[16];
#pragma unroll
        for (int q = 0; q < 16; ++q) { lo[q] = 0ull; jx[q] = 0ull; }
        gemmD<64, 64>(g_woutT, col0, sB0 + soff, sA1 + soff, lo, jx);
        float4 bb = *reinterpret_cast<const float4*>(b1v + col0);
        float bks[4] = {bb.x, bb.y, bb.z, bb.w};
#pragma unroll
        for (int ci = 0; ci < 4; ++ci) {
            ull bp = pack2(bks[ci], bks[ci]);
            ull cur[4];
#pragma unroll
            for (int p = 0; p < 4; ++p) {
                int q = ci * 4 + p;
                ull L = add2(lo[q], bp);
                float a, b; unpack2(L, a, b);
                float ta = tanhf(a), tb = tanhf(b);
                dth[q] = pack2(1.f - ta * ta, 1.f - tb * tb);
                cur[p] = mul2(jx[q], dth[q]);
                hd[q]  = cur[p];
            }
            stcol(sA0, t64, ci, soff, cur);    // curr -> sA0 (it0 reads sA0)
        }
    }
    __syncthreads();

    // ---- 8 Jh-power iterations, ping-pong buffers, 2 bars/iter
#pragma unroll 2
    for (int it = 0; it < KTERMS; ++it) {
        float* sAr = (it & 1) ? sA1 : sA0;   // curr in
        float* sBw = (it & 1) ? sB1 : sB0;   // gated out/in
        float* sAw = (it & 1) ? sA0 : sA1;   // curr out
        ull acc[16];
#pragma unroll
        for (int q = 0; q < 16; ++q) acc[q] = 0ull;
        gemmF<64, 64>(g_whT, col0, sAr + soff, acc);
#pragma unroll
        for (int ci = 0; ci < 4; ++ci) {
            ull gt[4];
#pragma unroll
            for (int p = 0; p < 4; ++p) gt[p] = mul2(acc[ci * 4 + p], gate[ci * 4 + p]);
            stcol(sBw, t64, ci, soff, gt);
        }
        __syncthreads();
#pragma unroll
        for (int q = 0; q < 16; ++q) acc[q] = 0ull;
        gemmF<64, 64>(g_woutT, col0, sBw + soff, acc);
#pragma unroll
        for (int ci = 0; ci < 4; ++ci) {
            ull cur[4];
#pragma unroll
            for (int p = 0; p < 4; ++p) {
                int q = ci * 4 + p;
                cur[p] = mul2(acc[q], dth[q]);
                hd[q] = add2(hd[q], cur[p]);
            }
            stcol(sAw, t64, ci, soff, cur);
        }
        __syncthreads();
    }

    // ---- write h_dot: thread owns cols col0..col0+3, rows row0+8*sub..+7
#pragma unroll
    for (int ci = 0; ci < 4; ++ci) {
#pragma unroll
        for (int p = 0; p < 4; ++p) {
            float a, b; unpack2(hd[ci * 4 + p], a, b);
            int r = row0 + (sub << 3) + 2 * p;
            out[r       * Hd + col0 + ci] = a;
            out[(r + 1) * Hd + col0 + ci] = b;
        }
    }
}

#define SMEM_BYTES ((4 * Hd + 2 * INd) * PITCH * 4)

extern "C" void kernel_launch(void* const* d_in, const int* in_sizes, int n_in,
                              void* d_out, int out_size) {
    (void)in_sizes; (void)n_in; (void)out_size;
    const float* h_   = (const float*)d_in[0];
    const float* x    = (const float*)d_in[1];
    const float* xdot = (const float*)d_in[2];
    const float* wx   = (const float*)d_in[3];
    const float* wh   = (const float*)d_in[4];
    const float* wout = (const float*)d_in[5];
    const float* b0   = (const float*)d_in[6];
    const float* b1   = (const float*)d_in[7];
    float* out = (float*)d_out;

    cudaFuncSetAttribute(fused_kernel, cudaFuncAttributeMaxDynamicSharedMemorySize, SMEM_BYTES);
    transpose_all<<<144, dim3(32, 8)>>>(wh, wout, wx);
    fused_kernel<<<NCTAS, NTHR, SMEM_BYTES>>>(h_, x, xdot, b0, b1, out);
}

// round 11
// speedup vs baseline: 3.7495x; 3.7495x over previous
#include <cuda_runtime.h>
#include <math.h>

#define Bsz    2048
#define Hd     256
#define INd    64
#define KTERMS 8
#define ROWS   8
#define NCTAS  256
#define NTHR   256
#define PITCH  12          // floats per smem act row (48B, odd 16B-granule stride)
#define SLOT   18          // u64 per export slot (144B, odd 16B-granule stride)

typedef unsigned long long ull;

// Pre-transposed weights (L2-resident)
__device__ float g_whT[Hd*Hd];     // whT[j*Hd+k]   = wh[k*Hd+j]
__device__ float g_woutT[Hd*Hd];   // woutT[j*Hd+k] = wout[k*Hd+j]
__device__ float g_wxT[INd*Hd];    // wxT[i*Hd+k]   = wx[k*INd+i]

// ---------------- packed f32x2 helpers ----------------
__device__ __forceinline__ ull pack2(float lo, float hi) {
    ull r; asm("mov.b64 %0, {%1,%2};" : "=l"(r) : "f"(lo), "f"(hi)); return r;
}
__device__ __forceinline__ void unpack2(ull v, float& lo, float& hi) {
    asm("mov.b64 {%0,%1}, %2;" : "=f"(lo), "=f"(hi) : "l"(v));
}
__device__ __forceinline__ ull fma2(ull a, ull b, ull c) {
    ull d; asm("fma.rn.f32x2 %0, %1, %2, %3;" : "=l"(d) : "l"(a), "l"(b), "l"(c)); return d;
}
__device__ __forceinline__ ull mul2(ull a, ull b) {
    ull d; asm("mul.rn.f32x2 %0, %1, %2;" : "=l"(d) : "l"(a), "l"(b)); return d;
}
__device__ __forceinline__ ull add2(ull a, ull b) {
    ull d; asm("add.rn.f32x2 %0, %1, %2;" : "=l"(d) : "l"(a), "l"(b)); return d;
}

struct Row4 { ull v[4]; };
__device__ __forceinline__ Row4 ldrow4(const float* p) {
    Row4 r;
    const ulonglong2* q = reinterpret_cast<const ulonglong2*>(p);
    ulonglong2 a = q[0], b = q[1];
    r.v[0]=a.x; r.v[1]=a.y; r.v[2]=b.x; r.v[3]=b.y;
    return r;
}

// C=4 partial GEMM for j-group g (plain, fma-accumulating).
// j = 4*NJ4*g + jm + 4*jd ; phys(j) = NJ4*g + jm*Q + jd
template<int NJ4, int Q>
__device__ __forceinline__ void gemmC4(const float* __restrict__ Wt, int col0, int g,
                                       const float* sIn, ull acc[16]) {
#pragma unroll
    for (int jm = 0; jm < 4; ++jm) {
        const float* wp = Wt + (4 * NJ4 * g + jm) * Hd + col0;
        const float* sp = sIn + (NJ4 * g + jm * Q) * PITCH;
#pragma unroll
        for (int jd = 0; jd < NJ4; ++jd) {
            float4 w4 = *reinterpret_cast<const float4*>(wp);
            Row4 v = ldrow4(sp);
            ull w0 = pack2(w4.x, w4.x), w1 = pack2(w4.y, w4.y);
            ull w2 = pack2(w4.z, w4.z), w3 = pack2(w4.w, w4.w);
#pragma unroll
            for (int t = 0; t < 4; ++t) {
                acc[t]    = fma2(w0, v.v[t], acc[t]);
                acc[4+t]  = fma2(w1, v.v[t], acc[4+t]);
                acc[8+t]  = fma2(w2, v.v[t], acc[8+t]);
                acc[12+t] = fma2(w3, v.v[t], acc[12+t]);
            }
            wp += 4 * Hd;
            sp += PITCH;
        }
    }
}

// Prefetch the first weight float4 of a gemm (issued before the preceding barriers).
template<int NJ4>
__device__ __forceinline__ float4 pfw(const float* __restrict__ Wt, int col0, int g) {
    return *reinterpret_cast<const float4*>(Wt + (4 * NJ4 * g) * Hd + col0);
}

// Peeled + prefetched variant: first (jm=0,jd=0) uses w4p and mul2-initializes acc.
template<int NJ4, int Q>
__device__ __forceinline__ void gemmC4_pf(const float* __restrict__ Wt, int col0, int g,
                                          const float* sIn, float4 w4p, ull acc[16]) {
    {   // peeled (jm=0, jd=0)
        Row4 v = ldrow4(sIn + (NJ4 * g) * PITCH);
        ull w0 = pack2(w4p.x, w4p.x), w1 = pack2(w4p.y, w4p.y);
        ull w2 = pack2(w4p.z, w4p.z), w3 = pack2(w4p.w, w4p.w);
#pragma unroll
        for (int t = 0; t < 4; ++t) {
            acc[t]    = mul2(w0, v.v[t]);
            acc[4+t]  = mul2(w1, v.v[t]);
            acc[8+t]  = mul2(w2, v.v[t]);
            acc[12+t] = mul2(w3, v.v[t]);
        }
    }
    {   // rest of jm=0
        const float* wp = Wt + (4 * NJ4 * g) * Hd + col0 + 4 * Hd;
        const float* sp = sIn + (NJ4 * g) * PITCH + PITCH;
#pragma unroll
        for (int jd = 1; jd < NJ4; ++jd) {
            float4 w4 = *reinterpret_cast<const float4*>(wp);
            Row4 v = ldrow4(sp);
            ull w0 = pack2(w4.x, w4.x), w1 = pack2(w4.y, w4.y);
            ull w2 = pack2(w4.z, w4.z), w3 = pack2(w4.w, w4.w);
#pragma unroll
            for (int t = 0; t < 4; ++t) {
                acc[t]    = fma2(w0, v.v[t], acc[t]);
                acc[4+t]  = fma2(w1, v.v[t], acc[4+t]);
                acc[8+t]  = fma2(w2, v.v[t], acc[8+t]);
                acc[12+t] = fma2(w3, v.v[t], acc[12+t]);
            }
            wp += 4 * Hd;
            sp += PITCH;
        }
    }
#pragma unroll
    for (int jm = 1; jm < 4; ++jm) {
        const float* wp = Wt + (4 * NJ4 * g + jm) * Hd + col0;
        const float* sp = sIn + (NJ4 * g + jm * Q) * PITCH;
#pragma unroll
        for (int jd = 0; jd < NJ4; ++jd) {
            float4 w4 = *reinterpret_cast<const float4*>(wp);
            Row4 v = ldrow4(sp);
            ull w0 = pack2(w4.x, w4.x), w1 = pack2(w4.y, w4.y);
            ull w2 = pack2(w4.z, w4.z), w3 = pack2(w4.w, w4.w);
#pragma unroll
            for (int t = 0; t < 4; ++t) {
                acc[t]    = fma2(w0, v.v[t], acc[t]);
                acc[4+t]  = fma2(w1, v.v[t], acc[4+t]);
                acc[8+t]  = fma2(w2, v.v[t], acc[8+t]);
                acc[12+t] = fma2(w3, v.v[t], acc[12+t]);
            }
            wp += 4 * Hd;
            sp += PITCH;
        }
    }
}

// export 16 u64 to this thread's slot (8 STS.128, conflict-free)
__device__ __forceinline__ void exportP(ull* p, const ull acc[16]) {
    ulonglong2* q = reinterpret_cast<ulonglong2*>(p);
#pragma unroll
    for (int c = 0; c < 8; ++c) q[c] = make_ulonglong2(acc[2*c], acc[2*c+1]);
}

// merge this thread's col (offset g*4 in each exporter slot) across 4 groups
__device__ __forceinline__ void mergeP(const ull* sRed, int quad, int g, ull m[4]) {
    m[0] = m[1] = m[2] = m[3] = 0ull;
#pragma unroll
    for (int gp = 0; gp < 4; ++gp) {
        const ull* p = sRed + (gp * 64 + quad) * SLOT + g * 4;
        ulonglong2 a = reinterpret_cast<const ulonglong2*>(p)[0];
        ulonglong2 b = reinterpret_cast<const ulonglong2*>(p)[1];
        m[0] = add2(m[0], a.x); m[1] = add2(m[1], a.y);
        m[2] = add2(m[2], b.x); m[3] = add2(m[3], b.y);
    }
}

__device__ __forceinline__ void st_slice(float* rowbase, const ull m[4]) {
    ulonglong2* p = reinterpret_cast<ulonglong2*>(rowbase);
    p[0] = make_ulonglong2(m[0], m[1]);
    p[1] = make_ulonglong2(m[2], m[3]);
}

// ---------------- merged transpose ----------------
__global__ void transpose_all(const float* __restrict__ wh,
                              const float* __restrict__ wout,
                              const float* __restrict__ wx) {
    __shared__ float tile[32][33];
    int b = blockIdx.x;
    const float* in; float* out; int rows, cols, bx;
    if (b < 64)       { in = wh;   out = g_whT;   rows = Hd; cols = Hd;  bx = b; }
    else if (b < 128) { in = wout; out = g_woutT; rows = Hd; cols = Hd;  bx = b - 64; }
    else              { in = wx;   out = g_wxT;   rows = Hd; cols = INd; bx = b - 128; }
    int nbx = cols / 32;
    int c0 = (bx % nbx) * 32, r0 = (bx / nbx) * 32;
    for (int dy = threadIdx.y; dy < 32; dy += 8)
        tile[dy][threadIdx.x] = in[(r0 + dy) * cols + (c0 + threadIdx.x)];
    __syncthreads();
    for (int dy = threadIdx.y; dy < 32; dy += 8)
        out[(c0 + dy) * rows + (r0 + threadIdx.x)] = tile[threadIdx.x][dy];
}

// ---------------- fused vector-field kernel (2 CTAs / SM) ----------------
__global__ void __launch_bounds__(NTHR, 2)
fused_kernel(const float* __restrict__ hin, const float* __restrict__ xin,
             const float* __restrict__ xdin, const float* __restrict__ b0,
             const float* __restrict__ b1, float* __restrict__ out) {
    extern __shared__ __align__(16) char smraw[];
    ull*   sRed = reinterpret_cast<ull*>(smraw);                 // [256][SLOT]
    float* sA   = reinterpret_cast<float*>(sRed + NTHR * SLOT);  // [256][PITCH]
    float* sB   = sA + Hd * PITCH;                               // [256][PITCH]
    float* sXx  = sB + Hd * PITCH;                               // [64][PITCH]
    float* sXd  = sXx + INd * PITCH;                             // [64][PITCH]

    const int tid   = threadIdx.x;
    const int warp  = tid >> 5;
    const int lane  = tid & 31;
    const int g     = warp >> 1;                 // j-group 0..3 (warp-uniform)
    const int quad  = ((warp & 1) << 5) + lane;  // 0..63
    const int col0  = quad << 2;
    const int mycol = col0 + g;
    const int myrow = quad + (g << 6);           // phys(mycol)
    ull* myslot = sRed + (g * 64 + quad) * SLOT;
    const int row0  = blockIdx.x * ROWS;

    // ---- stage inputs (transposed + phys-permuted); 2048 = 256*8, no tail
    for (int e = tid; e < ROWS * Hd; e += NTHR) {
        int r = e >> 8, j = e & 255;
        int pr = (j >> 2) + ((j & 3) << 6);
        sA[pr * PITCH + r] = hin[(row0 + r) * Hd + j];
    }
    for (int e = tid; e < ROWS * INd; e += NTHR) {
        int r = e >> 6, i = e & 63;
        int pr = (i >> 2) + ((i & 3) << 4);
        sXx[pr * PITCH + r] = xin[(row0 + r) * INd + i];
        sXd[pr * PITCH + r] = xdin[(row0 + r) * INd + i];
    }
    __syncthreads();

    ull gate[4], dth[4], hd[4];
    ull acc[16];

    // ---- P1: l1 = x@wxT + h@whT + b0 -> gate, relu(sB)
    {
        float4 wpx = pfw<4>(g_wxT, col0, g);
        gemmC4_pf<4, 16>(g_wxT, col0, g, sXx, wpx, acc);   // peel-init
    }
    gemmC4<16, 64>(g_whT, col0, g, sA, acc);
    exportP(myslot, acc);
    float4 wp2 = pfw<4>(g_wxT, col0, g);                   // prefetch P2 weights
    __syncthreads();
    {
        ull m[4];
        mergeP(sRed, quad, g, m);
        float bk = b0[mycol];
        ull bp = pack2(bk, bk);
        ull relu[4];
#pragma unroll
        for (int t = 0; t < 4; ++t) {
            m[t] = add2(m[t], bp);
            float a, b; unpack2(m[t], a, b);
            float ga = (a > 0.f) ? 1.f : 0.f;
            float gb = (b > 0.f) ? 1.f : 0.f;
            gate[t] = pack2(ga, gb);
            relu[t] = pack2(ga * a, gb * b);
        }
        st_slice(sB + myrow * PITCH, relu);
    }
    __syncthreads();

    // ---- P2: uu = xdot@wxT ; gated-u -> sA
    gemmC4_pf<4, 16>(g_wxT, col0, g, sXd, wp2, acc);
    exportP(myslot, acc);
    float4 wpo = pfw<16>(g_woutT, col0, g);                // prefetch P3/P4 weights
    __syncthreads();
    {
        ull m[4];
        mergeP(sRed, quad, g, m);
#pragma unroll
        for (int t = 0; t < 4; ++t) m[t] = mul2(m[t], gate[t]);
        st_slice(sA + myrow * PITCH, m);
    }
    __syncthreads();

    // ---- P3: lout = relu@woutT + b1 -> dth (registers only)
    gemmC4_pf<16, 64>(g_woutT, col0, g, sB, wpo, acc);
    exportP(myslot, acc);
    __syncthreads();
    {
        ull m[4];
        mergeP(sRed, quad, g, m);
        float bk = b1[mycol];
        ull bp = pack2(bk, bk);
#pragma unroll
        for (int t = 0; t < 4; ++t) {
            ull L = add2(m[t], bp);
            float a, b; unpack2(L, a, b);
            float ta = tanhf(a), tb = tanhf(b);
            dth[t] = pack2(1.f - ta * ta, 1.f - tb * tb);
        }
    }
    __syncthreads();

    // ---- P4: jx = gated-u@woutT ; curr = dth*jx -> sA ; hdot = curr
    gemmC4_pf<16, 64>(g_woutT, col0, g, sA, wpo, acc);     // same first weights as P3
    exportP(myslot, acc);
    float4 wph = pfw<16>(g_whT, col0, g);                  // prefetch iter-0 wh weights
    __syncthreads();
    {
        ull m[4];
        mergeP(sRed, quad, g, m);
#pragma unroll
        for (int t = 0; t < 4; ++t) m[t] = mul2(m[t], dth[t]);
        st_slice(sA + myrow * PITCH, m);
#pragma unroll
        for (int t = 0; t < 4; ++t) hd[t] = m[t];
    }
    __syncthreads();

    // ---- 8 Jh-power iterations: curr = dth * ((gate * (curr@whT)) @ woutT)
    for (int it = 0; it < KTERMS; ++it) {
        gemmC4_pf<16, 64>(g_whT, col0, g, sA, wph, acc);
        exportP(myslot, acc);
        float4 wpo2 = pfw<16>(g_woutT, col0, g);           // prefetch wout weights
        __syncthreads();
        {
            ull m[4];
            mergeP(sRed, quad, g, m);
#pragma unroll
            for (int t = 0; t < 4; ++t) m[t] = mul2(m[t], gate[t]);
            st_slice(sB + myrow * PITCH, m);
        }
        __syncthreads();
        gemmC4_pf<16, 64>(g_woutT, col0, g, sB, wpo2, acc);
        exportP(myslot, acc);
        wph = pfw<16>(g_whT, col0, g);                     // prefetch next iter's wh
        __syncthreads();
        {
            ull m[4];
            mergeP(sRed, quad, g, m);
#pragma unroll
            for (int t = 0; t < 4; ++t) m[t] = mul2(m[t], dth[t]);
            st_slice(sA + myrow * PITCH, m);               // store first (critical path)
#pragma unroll
            for (int t = 0; t < 4; ++t) hd[t] = add2(hd[t], m[t]);
        }
        __syncthreads();
    }

    // ---- write h_dot: thread owns (mycol, rows row0..row0+7)
#pragma unroll
    for (int t = 0; t < 4; ++t) {
        float a, b; unpack2(hd[t], a, b);
        out[(row0 + 2*t)     * Hd + mycol] = a;
        out[(row0 + 2*t + 1) * Hd + mycol] = b;
    }
}

#define SMEM_BYTES (NTHR * SLOT * 8 + (2 * Hd + 2 * INd) * PITCH * 4)

extern "C" void kernel_launch(void* const* d_in, const int* in_sizes, int n_in,
                              void* d_out, int out_size) {
    (void)in_sizes; (void)n_in; (void)out_size;
    const float* h_   = (const float*)d_in[0];
    const float* x    = (const float*)d_in[1];
    const float* xdot = (const float*)d_in[2];
    const float* wx   = (const float*)d_in[3];
    const float* wh   = (const float*)d_in[4];
    const float* wout = (const float*)d_in[5];
    const float* b0   = (const float*)d_in[6];
    const float* b1   = (const float*)d_in[7];
    float* out = (float*)d_out;

    cudaFuncSetAttribute(fused_kernel, cudaFuncAttributeMaxDynamicSharedMemorySize, SMEM_BYTES);
    transpose_all<<<144, dim3(32, 8)>>>(wh, wout, wx);
    fused_kernel<<<NCTAS, NTHR, SMEM_BYTES>>>(h_, x, xdot, b0, b1, out);
}

// round 12
// speedup vs baseline: 4.0931x; 1.0917x over previous
#include <cuda_runtime.h>
#include <math.h>

#define Bsz    2048
#define Hd     256
#define INd    64
#define KTERMS 8
#define NTHR   256
#define PITCH  12          // floats per smem act row (48B, odd 16B-granule stride)
#define SLOT   18          // u64 per export slot (144B, odd 16B-granule stride)

typedef unsigned long long ull;

// Pre-transposed weights (L2-resident)
__device__ float g_whT[Hd*Hd];
__device__ float g_woutT[Hd*Hd];
__device__ float g_wxT[INd*Hd];

// ---------------- packed f32x2 helpers ----------------
__device__ __forceinline__ ull pack2(float lo, float hi) {
    ull r; asm("mov.b64 %0, {%1,%2};" : "=l"(r) : "f"(lo), "f"(hi)); return r;
}
__device__ __forceinline__ void unpack2(ull v, float& lo, float& hi) {
    asm("mov.b64 {%0,%1}, %2;" : "=f"(lo), "=f"(hi) : "l"(v));
}
__device__ __forceinline__ ull fma2(ull a, ull b, ull c) {
    ull d; asm("fma.rn.f32x2 %0, %1, %2, %3;" : "=l"(d) : "l"(a), "l"(b), "l"(c)); return d;
}
__device__ __forceinline__ ull mul2(ull a, ull b) {
    ull d; asm("mul.rn.f32x2 %0, %1, %2;" : "=l"(d) : "l"(a), "l"(b)); return d;
}
__device__ __forceinline__ ull add2(ull a, ull b) {
    ull d; asm("add.rn.f32x2 %0, %1, %2;" : "=l"(d) : "l"(a), "l"(b)); return d;
}

// load PAIRS u64 from an act row
template<int PAIRS>
__device__ __forceinline__ void ldrowP(const float* p, ull v[PAIRS]) {
    ulonglong2 a = *reinterpret_cast<const ulonglong2*>(p);
    v[0] = a.x; v[1] = a.y;
    if (PAIRS == 3) {
        v[2] = reinterpret_cast<const ull*>(p)[2];
    } else if (PAIRS == 4) {
        ulonglong2 b = reinterpret_cast<const ulonglong2*>(p)[1];
        v[2] = b.x; v[3] = b.y;
    }
}

// C=4 partial GEMM for j-group g. j = 4*NJ4*g + jm + 4*jd ; phys(j) = NJ4*g + jm*Q + jd
template<int PAIRS, int NJ4, int Q>
__device__ __forceinline__ void gemmC4(const float* __restrict__ Wt, int col0, int g,
                                       const float* sIn, ull acc[4 * PAIRS]) {
#pragma unroll
    for (int jm = 0; jm < 4; ++jm) {
        const float* wp = Wt + (4 * NJ4 * g + jm) * Hd + col0;
        const float* sp = sIn + (NJ4 * g + jm * Q) * PITCH;
#pragma unroll
        for (int jd = 0; jd < NJ4; ++jd) {
            float4 w4 = *reinterpret_cast<const float4*>(wp);
            ull v[PAIRS];
            ldrowP<PAIRS>(sp, v);
            ull w0 = pack2(w4.x, w4.x), w1 = pack2(w4.y, w4.y);
            ull w2 = pack2(w4.z, w4.z), w3 = pack2(w4.w, w4.w);
#pragma unroll
            for (int t = 0; t < PAIRS; ++t) {
                acc[t]             = fma2(w0, v[t], acc[t]);
                acc[PAIRS + t]     = fma2(w1, v[t], acc[PAIRS + t]);
                acc[2 * PAIRS + t] = fma2(w2, v[t], acc[2 * PAIRS + t]);
                acc[3 * PAIRS + t] = fma2(w3, v[t], acc[3 * PAIRS + t]);
            }
            wp += 4 * Hd;
            sp += PITCH;
        }
    }
}

// export partials: col c at slot offset c*4 (stride 4 u64 per col, both PAIRS)
template<int PAIRS>
__device__ __forceinline__ void exportP(ull* p, const ull acc[4 * PAIRS]) {
#pragma unroll
    for (int c = 0; c < 4; ++c) {
        ull* b = p + c * 4;
        reinterpret_cast<ulonglong2*>(b)[0] =
            make_ulonglong2(acc[c * PAIRS + 0], acc[c * PAIRS + 1]);
        if (PAIRS == 3) {
            b[2] = acc[c * PAIRS + 2];
        } else {
            reinterpret_cast<ulonglong2*>(b)[1] =
                make_ulonglong2(acc[c * PAIRS + 2], acc[c * PAIRS + 3]);
        }
    }
}

// merge this thread's col (offset g*4 in each exporter slot) across 4 groups
template<int PAIRS>
__device__ __forceinline__ void mergeP(const ull* sRed, int quad, int g, ull m[PAIRS]) {
#pragma unroll
    for (int t = 0; t < PAIRS; ++t) m[t] = 0ull;
#pragma unroll
    for (int gp = 0; gp < 4; ++gp) {
        const ull* p = sRed + (gp * 64 + quad) * SLOT + g * 4;
        ulonglong2 a = reinterpret_cast<const ulonglong2*>(p)[0];
        m[0] = add2(m[0], a.x); m[1] = add2(m[1], a.y);
        if (PAIRS == 3) {
            m[2] = add2(m[2], p[2]);
        } else {
            ulonglong2 b = reinterpret_cast<const ulonglong2*>(p)[1];
            m[2] = add2(m[2], b.x); m[3] = add2(m[3], b.y);
        }
    }
}

template<int PAIRS>
__device__ __forceinline__ void st_slice(float* rowbase, const ull m[PAIRS]) {
    ull* p = reinterpret_cast<ull*>(rowbase);
    reinterpret_cast<ulonglong2*>(p)[0] = make_ulonglong2(m[0], m[1]);
    if (PAIRS == 3) {
        p[2] = m[2];
    } else {
        reinterpret_cast<ulonglong2*>(p)[1] = make_ulonglong2(m[2], m[3]);
    }
}

// ---------------- merged transpose ----------------
__global__ void transpose_all(const float* __restrict__ wh,
                              const float* __restrict__ wout,
                              const float* __restrict__ wx) {
    __shared__ float tile[32][33];
    int b = blockIdx.x;
    const float* in; float* out; int rows, cols, bx;
    if (b < 64)       { in = wh;   out = g_whT;   rows = Hd; cols = Hd;  bx = b; }
    else if (b < 128) { in = wout; out = g_woutT; rows = Hd; cols = Hd;  bx = b - 64; }
    else              { in = wx;   out = g_wxT;   rows = Hd; cols = INd; bx = b - 128; }
    int nbx = cols / 32;
    int c0 = (bx % nbx) * 32, r0 = (bx / nbx) * 32;
    for (int dy = threadIdx.y; dy < 32; dy += 8)
        tile[dy][threadIdx.x] = in[(r0 + dy) * cols + (c0 + threadIdx.x)];
    __syncthreads();
    for (int dy = threadIdx.y; dy < 32; dy += 8)
        out[(c0 + dy) * rows + (r0 + threadIdx.x)] = tile[threadIdx.x][dy];
}

// ---------------- the full pipeline, parameterized on PAIRS (rows = 2*PAIRS) ----------------
template<int PAIRS>
__device__ __forceinline__ void pipeline(
    const float* __restrict__ hin, const float* __restrict__ xin,
    const float* __restrict__ xdin, const float* __restrict__ b0,
    const float* __restrict__ b1, float* __restrict__ out,
    ull* sRed, float* sA, float* sB, float* sXx, float* sXd, int row0) {

    const int ROWSL = 2 * PAIRS;
    const int tid   = threadIdx.x;
    const int warp  = tid >> 5;
    const int lane  = tid & 31;
    const int g     = warp >> 1;                 // j-group 0..3 (warp-uniform)
    const int quad  = ((warp & 1) << 5) + lane;  // 0..63
    const int col0  = quad << 2;
    const int mycol = col0 + g;
    const int myrow = quad + (g << 6);           // phys(mycol)
    ull* myslot = sRed + (g * 64 + quad) * SLOT;

    // hoist bias loads (overlap with staging)
    float bk0 = b0[mycol];
    float bk1 = b1[mycol];

    // ---- stage inputs (transposed + phys-permuted). NTHR == Hd: thread = one j column.
    {
        int pr = (tid >> 2) + ((tid & 3) << 6);
#pragma unroll
        for (int r = 0; r < ROWSL; ++r)
            sA[pr * PITCH + r] = hin[(row0 + r) * Hd + tid];
        if (tid < 2 * INd) {
            int i = tid & 63;
            int px = (i >> 2) + ((i & 3) << 4);
            const float* src = (tid < INd) ? xin : xdin;
            float* dst = (tid < INd) ? sXx : sXd;
#pragma unroll
            for (int r = 0; r < ROWSL; ++r)
                dst[px * PITCH + r] = src[(row0 + r) * INd + i];
        }
    }
    __syncthreads();

    ull gate[PAIRS], dth[PAIRS], hd[PAIRS];
    ull acc[4 * PAIRS];

    // ---- P1: l1 = x@wxT + h@whT + b0 -> gate, relu(sB)
#pragma unroll
    for (int q = 0; q < 4 * PAIRS; ++q) acc[q] = 0ull;
    gemmC4<PAIRS, 4, 16>(g_wxT, col0, g, sXx, acc);
    gemmC4<PAIRS, 16, 64>(g_whT, col0, g, sA, acc);
    exportP<PAIRS>(myslot, acc);
    __syncthreads();
    {
        ull m[PAIRS];
        mergeP<PAIRS>(sRed, quad, g, m);
        ull bp = pack2(bk0, bk0);
        ull relu[PAIRS];
#pragma unroll
        for (int t = 0; t < PAIRS; ++t) {
            m[t] = add2(m[t], bp);
            float a, b; unpack2(m[t], a, b);
            float ga = (a > 0.f) ? 1.f : 0.f;
            float gb = (b > 0.f) ? 1.f : 0.f;
            gate[t] = pack2(ga, gb);
            relu[t] = pack2(ga * a, gb * b);
        }
        st_slice<PAIRS>(sB + myrow * PITCH, relu);
    }
    __syncthreads();

    // ---- P2: uu = xdot@wxT ; gated-u -> sA
#pragma unroll
    for (int q = 0; q < 4 * PAIRS; ++q) acc[q] = 0ull;
    gemmC4<PAIRS, 4, 16>(g_wxT, col0, g, sXd, acc);
    exportP<PAIRS>(myslot, acc);
    __syncthreads();
    {
        ull m[PAIRS];
        mergeP<PAIRS>(sRed, quad, g, m);
#pragma unroll
        for (int t = 0; t < PAIRS; ++t) m[t] = mul2(m[t], gate[t]);
        st_slice<PAIRS>(sA + myrow * PITCH, m);
    }
    __syncthreads();

    // ---- P3: lout = relu@woutT + b1 -> dth
#pragma unroll
    for (int q = 0; q < 4 * PAIRS; ++q) acc[q] = 0ull;
    gemmC4<PAIRS, 16, 64>(g_woutT, col0, g, sB, acc);
    exportP<PAIRS>(myslot, acc);
    __syncthreads();
    {
        ull m[PAIRS];
        mergeP<PAIRS>(sRed, quad, g, m);
        ull bp = pack2(bk1, bk1);
#pragma unroll
        for (int t = 0; t < PAIRS; ++t) {
            ull L = add2(m[t], bp);
            float a, b; unpack2(L, a, b);
            float ta = tanhf(a), tb = tanhf(b);
            dth[t] = pack2(1.f - ta * ta, 1.f - tb * tb);
        }
    }
    __syncthreads();

    // ---- P4: jx = gated-u@woutT ; curr = dth*jx -> sA ; hdot = curr
#pragma unroll
    for (int q = 0; q < 4 * PAIRS; ++q) acc[q] = 0ull;
    gemmC4<PAIRS, 16, 64>(g_woutT, col0, g, sA, acc);
    exportP<PAIRS>(myslot, acc);
    __syncthreads();
    {
        ull m[PAIRS];
        mergeP<PAIRS>(sRed, quad, g, m);
#pragma unroll
        for (int t = 0; t < PAIRS; ++t) m[t] = mul2(m[t], dth[t]);
        st_slice<PAIRS>(sA + myrow * PITCH, m);
#pragma unroll
        for (int t = 0; t < PAIRS; ++t) hd[t] = m[t];
    }
    __syncthreads();

    // ---- 8 Jh-power iterations
    for (int it = 0; it < KTERMS; ++it) {
#pragma unroll
        for (int q = 0; q < 4 * PAIRS; ++q) acc[q] = 0ull;
        gemmC4<PAIRS, 16, 64>(g_whT, col0, g, sA, acc);
        exportP<PAIRS>(myslot, acc);
        __syncthreads();
        {
            ull m[PAIRS];
            mergeP<PAIRS>(sRed, quad, g, m);
#pragma unroll
            for (int t = 0; t < PAIRS; ++t) m[t] = mul2(m[t], gate[t]);
            st_slice<PAIRS>(sB + myrow * PITCH, m);
        }
        __syncthreads();
#pragma unroll
        for (int q = 0; q < 4 * PAIRS; ++q) acc[q] = 0ull;
        gemmC4<PAIRS, 16, 64>(g_woutT, col0, g, sB, acc);
        exportP<PAIRS>(myslot, acc);
        __syncthreads();
        {
            ull m[PAIRS];
            mergeP<PAIRS>(sRed, quad, g, m);
#pragma unroll
            for (int t = 0; t < PAIRS; ++t) m[t] = mul2(m[t], dth[t]);
            st_slice<PAIRS>(sA + myrow * PITCH, m);
#pragma unroll
            for (int t = 0; t < PAIRS; ++t) hd[t] = add2(hd[t], m[t]);
        }
        __syncthreads();
    }

    // ---- write h_dot
#pragma unroll
    for (int t = 0; t < PAIRS; ++t) {
        float a, b; unpack2(hd[t], a, b);
        out[(row0 + 2 * t)     * Hd + mycol] = a;
        out[(row0 + 2 * t + 1) * Hd + mycol] = b;
    }
}

// ---------------- fused kernel: 296 CTAs, one wave, 4+3 pairs per SM ----------------
__global__ void __launch_bounds__(NTHR, 2)
fused_kernel(const float* __restrict__ hin, const float* __restrict__ xin,
             const float* __restrict__ xdin, const float* __restrict__ b0,
             const float* __restrict__ b1, float* __restrict__ out) {
    extern __shared__ __align__(16) char smraw[];
    ull*   sRed = reinterpret_cast<ull*>(smraw);
    float* sA   = reinterpret_cast<float*>(sRed + NTHR * SLOT);
    float* sB   = sA + Hd * PITCH;
    float* sXx  = sB + Hd * PITCH;
    float* sXd  = sXx + INd * PITCH;

    int bid = blockIdx.x;
    if (bid < 148) {
        pipeline<4>(hin, xin, xdin, b0, b1, out, sRed, sA, sB, sXx, sXd, bid * 8);
    } else {
        int row0 = 148 * 8 + (bid - 148) * 6;
        if (row0 + 6 > Bsz) return;               // tail CTAs (rows >= 2048) idle
        pipeline<3>(hin, xin, xdin, b0, b1, out, sRed, sA, sB, sXx, sXd, row0);
    }
}

#define SMEM_BYTES (NTHR * SLOT * 8 + (2 * Hd + 2 * INd) * PITCH * 4)

extern "C" void kernel_launch(void* const* d_in, const int* in_sizes, int n_in,
                              void* d_out, int out_size) {
    (void)in_sizes; (void)n_in; (void)out_size;
    const float* h_   = (const float*)d_in[0];
    const float* x    = (const float*)d_in[1];
    const float* xdot = (const float*)d_in[2];
    const float* wx   = (const float*)d_in[3];
    const float* wh   = (const float*)d_in[4];
    const float* wout = (const float*)d_in[5];
    const float* b0   = (const float*)d_in[6];
    const float* b1   = (const float*)d_in[7];
    float* out = (float*)d_out;

    cudaFuncSetAttribute(fused_kernel, cudaFuncAttributeMaxDynamicSharedMemorySize, SMEM_BYTES);
    transpose_all<<<144, dim3(32, 8)>>>(wh, wout, wx);
    fused_kernel<<<296, NTHR, SMEM_BYTES>>>(h_, x, xdot, b0, b1, out);
}